// round 4
// baseline (speedup 1.0000x reference)
#include <cuda_runtime.h>

// Custom_Decoder: est = einsum('bcle,we->bclw', x, wt) then overlap_and_add(step=8)
// B=8, C=2, FRAMES=3999, E=512, W=16, STEP=8 -> out [8,2,32000] fp32
//
// Fused: out[bc, 16p + (0..7)]  = x[2p]  . wt[0..8)  + x[2p-1] . wt[8..16)
//        out[bc, 16p + (8..15)] = x[2p+1]. wt[0..8)  + x[2p]   . wt[8..16)
// Each thread computes TWO adjacent pairs (p0=2g, p1=2g+1) so every weight
// LDS feeds 8 FFMA2 instead of 4 (halves the dominant LDS traffic).

#define FRAMES 3999
#define E_DIM 512
#define W_DIM 16
#define N_BC 16
#define PAIRS 2000           // per (b,c)
#define GROUPS 1000          // per (b,c): 2 pairs per group
#define OUT_T 32000
#define KS 8                 // k-split lanes per group
#define GROUPS_PER_BLOCK 16
#define NTHREADS 128         // 16 groups * 8 ks lanes

typedef unsigned long long ull;

__device__ __forceinline__ void ffma2(ull &d, ull a, ull b) {
    asm("fma.rn.f32x2 %0, %1, %2, %0;" : "+l"(d) : "l"(a), "l"(b));
}

__device__ __forceinline__ float lo(ull v) { return __uint_as_float((unsigned)(v & 0xffffffffu)); }
__device__ __forceinline__ float hi(ull v) { return __uint_as_float((unsigned)(v >> 32)); }

__global__ __launch_bounds__(NTHREADS, 5)   // cap regs at 102 -> 5 CTAs/SM
void decoder_oadd_kernel(const float* __restrict__ x,
                         const float* __restrict__ wt,
                         float* __restrict__ out)
{
    __shared__ __align__(16) float wsm[W_DIM * E_DIM];   // 32 KB

    const int tid = threadIdx.x;

    // stage weight into smem (coalesced float4): 8192 floats / 128 thr = 16 ea
#pragma unroll
    for (int j = 0; j < (W_DIM * E_DIM) / (4 * NTHREADS); j++) {
        int idx = (j * NTHREADS + tid) * 4;
        *(float4*)(wsm + idx) = *(const float4*)(wt + idx);
    }
    __syncthreads();

    const int ks = tid & (KS - 1);                         // 0..7 k slice
    const int G  = blockIdx.x * GROUPS_PER_BLOCK + (tid >> 3);  // 0..15999
    const int bc = G / GROUPS;
    const int g  = G - bc * GROUPS;
    const int p0 = 2 * g;                                  // pairs p0, p0+1

    // frames needed: fm1=2p0-1, f0=2p0, f1=2p0+1, f2=2p0+2, f3=2p0+3
    const float* base = x + (size_t)bc * FRAMES * E_DIM + (size_t)(2 * p0) * E_DIM;
    const ulonglong2* __restrict__ Pm1 = (const ulonglong2*)(base - E_DIM);
    const ulonglong2* __restrict__ P0  = (const ulonglong2*)(base);
    const ulonglong2* __restrict__ P1  = (const ulonglong2*)(base + E_DIM);
    const ulonglong2* __restrict__ P2  = (const ulonglong2*)(base + 2 * E_DIM);
    const ulonglong2* __restrict__ P3  = (const ulonglong2*)(base + 3 * E_DIM);
    const bool vA = (p0 > 0);            // frame 2p0-1 exists
    const bool vC = (p0 < PAIRS - 2);    // frame 2p0+3 <= 3998

    // accumulators: pair0 -> a0/a1, pair1 -> b0/b1 (each ull = 2 packed fp32)
    ull a0[8], a1[8], b0[8], b1[8];
#pragma unroll
    for (int r = 0; r < 8; r++) { a0[r] = 0; a1[r] = 0; b0[r] = 0; b1[r] = 0; }

    // Lane ks covers K elements {32*i + 4*ks + (0..3)}.  The 8 ks-lanes of a
    // group read one contiguous 128B line per frame per iter (coalesced LDG,
    // conflict-free LDS).
#pragma unroll 8
    for (int i = 0; i < 16; i++) {
        const int off = i * 32 + ks * 4;
        const int v   = off >> 2;

        ulonglong2 xm1 = vA ? Pm1[v] : make_ulonglong2(0, 0);
        ulonglong2 x0  = P0[v];
        ulonglong2 x1  = P1[v];
        ulonglong2 x2  = P2[v];
        ulonglong2 x3  = vC ? P3[v] : make_ulonglong2(0, 0);

#pragma unroll
        for (int r = 0; r < 8; r++) {
            ulonglong2 wl = *(const ulonglong2*)(wsm + r * E_DIM + off);        // wt[r]
            ulonglong2 wh = *(const ulonglong2*)(wsm + (r + 8) * E_DIM + off);  // wt[r+8]
            // pair0: A=xm1 B=x0 C=x1
            ffma2(a0[r], x0.x,  wl.x);  ffma2(a0[r], x0.y,  wl.y);
            ffma2(a0[r], xm1.x, wh.x);  ffma2(a0[r], xm1.y, wh.y);
            ffma2(a1[r], x1.x,  wl.x);  ffma2(a1[r], x1.y,  wl.y);
            ffma2(a1[r], x0.x,  wh.x);  ffma2(a1[r], x0.y,  wh.y);
            // pair1: A=x1 B=x2 C=x3
            ffma2(b0[r], x2.x,  wl.x);  ffma2(b0[r], x2.y,  wl.y);
            ffma2(b0[r], x1.x,  wh.x);  ffma2(b0[r], x1.y,  wh.y);
            ffma2(b1[r], x3.x,  wl.x);  ffma2(b1[r], x3.y,  wl.y);
            ffma2(b1[r], x2.x,  wh.x);  ffma2(b1[r], x2.y,  wh.y);
        }
    }

    // horizontal (packed-pair) add, then reduce over the 8 ks lanes
    float s[32];
#pragma unroll
    for (int r = 0; r < 8; r++) {
        s[r]      = lo(a0[r]) + hi(a0[r]);
        s[8 + r]  = lo(a1[r]) + hi(a1[r]);
        s[16 + r] = lo(b0[r]) + hi(b0[r]);
        s[24 + r] = lo(b1[r]) + hi(b1[r]);
    }
#pragma unroll
    for (int m = 1; m <= 4; m <<= 1) {
#pragma unroll
        for (int j = 0; j < 32; j++)
            s[j] += __shfl_xor_sync(0xffffffffu, s[j], m);
    }

    if (ks == 0) {
        float* o = out + (size_t)bc * OUT_T + (size_t)p0 * 16;   // 32 contiguous floats
#pragma unroll
        for (int q = 0; q < 8; q++)
            *(float4*)(o + 4 * q) = make_float4(s[4*q], s[4*q+1], s[4*q+2], s[4*q+3]);
    }
}

extern "C" void kernel_launch(void* const* d_in, const int* in_sizes, int n_in,
                              void* d_out, int out_size)
{
    const float* x;
    const float* wt;
    if (in_sizes[0] > in_sizes[1]) { x = (const float*)d_in[0]; wt = (const float*)d_in[1]; }
    else                           { x = (const float*)d_in[1]; wt = (const float*)d_in[0]; }

    const int total_groups = N_BC * GROUPS;                  // 16000
    const int grid = total_groups / GROUPS_PER_BLOCK;        // 1000 blocks
    decoder_oadd_kernel<<<grid, NTHREADS>>>(x, wt, (float*)d_out);
}

// round 6
// speedup vs baseline: 1.2647x; 1.2647x over previous
#include <cuda_runtime.h>

// Custom_Decoder: est = einsum('bcle,we->bclw', x, wt) then overlap_and_add(step=8)
// B=8, C=2, FRAMES=3999, E=512, W=16, STEP=8 -> out [8,2,32000] fp32
//
// Fused: out[bc, 16p + r]     = x[2p]  . wt[r] + x[2p-1] . wt[8+r]   (r=0..7)
//        out[bc, 16p + 8 + r] = x[2p+1]. wt[r] + x[2p]   . wt[8+r]
//
// R4 layout: thread = (2 adjacent pairs) x (half the rows).  16 accumulators
// (same reg budget as the best kernel) but only 8 weight LDS per granule.
// Group = 2 pairs, served by 16 threads = 8 ks-lanes x 2 row-halves.

#define FRAMES 3999
#define E_DIM 512
#define W_DIM 16
#define N_BC 16
#define PAIRS 2000
#define GROUPS 1000          // per (b,c): 2 pairs per group
#define OUT_T 32000
#define GROUPS_PER_BLOCK 16
#define NTHREADS 256         // 16 groups * 16 threads

typedef unsigned long long ull;

__device__ __forceinline__ void ffma2(ull &d, ull a, ull b) {
    asm("fma.rn.f32x2 %0, %1, %2, %0;" : "+l"(d) : "l"(a), "l"(b));
}
__device__ __forceinline__ float lo(ull v) { return __uint_as_float((unsigned)(v & 0xffffffffu)); }
__device__ __forceinline__ float hi(ull v) { return __uint_as_float((unsigned)(v >> 32)); }

__global__ __launch_bounds__(NTHREADS, 3)   // cap regs at 85 -> 3 CTAs/SM (24 warps)
void decoder_oadd_kernel(const float* __restrict__ x,
                         const float* __restrict__ wt,
                         float* __restrict__ out)
{
    __shared__ __align__(16) float wsm[W_DIM * E_DIM];   // 32 KB

    const int tid = threadIdx.x;

    // stage weight into smem (coalesced float4): 8192 floats / 256 thr = 8 ea
#pragma unroll
    for (int j = 0; j < (W_DIM * E_DIM) / (4 * NTHREADS); j++) {
        int idx = (j * NTHREADS + tid) * 4;
        *(float4*)(wsm + idx) = *(const float4*)(wt + idx);
    }
    __syncthreads();

    const int ks = tid & 7;              // k slice (K elems 32i + 4ks + 0..3)
    const int rh = (tid >> 3) & 1;       // row half: rows rh*4..rh*4+3 (+8)
    const int gl = tid >> 4;             // group within block
    const int G  = blockIdx.x * GROUPS_PER_BLOCK + gl;   // 0..15999
    const int bc = G / GROUPS;
    const int g  = G - bc * GROUPS;
    const int p0 = 2 * g;                // pairs p0, p0+1
    const int rb = rh * 4;               // first row of this thread's row set

    // frames: fm1=2p0-1, f0, f1, f2, f3=2p0+3
    const float* base = x + (size_t)bc * FRAMES * E_DIM + (size_t)(2 * p0) * E_DIM;
    const ulonglong2* __restrict__ Pm1 = (const ulonglong2*)(base - E_DIM);
    const ulonglong2* __restrict__ P0  = (const ulonglong2*)(base);
    const ulonglong2* __restrict__ P1  = (const ulonglong2*)(base + E_DIM);
    const ulonglong2* __restrict__ P2  = (const ulonglong2*)(base + 2 * E_DIM);
    const ulonglong2* __restrict__ P3  = (const ulonglong2*)(base + 3 * E_DIM);
    const bool vA = (p0 > 0);
    const bool vC = (p0 < PAIRS - 2);    // frame 2p0+3 exists

    // 16 accumulators: a0/a1 = pair0, b0/b1 = pair1; index j -> row rb+j
    ull a0[4], a1[4], b0[4], b1[4];
#pragma unroll
    for (int j = 0; j < 4; j++) { a0[j] = 0; a1[j] = 0; b0[j] = 0; b1[j] = 0; }

    const float* wl_base = wsm + rb * E_DIM;            // rows rb..rb+3
    const float* wh_base = wsm + (8 + rb) * E_DIM;      // rows 8+rb..8+rb+3

#pragma unroll
    for (int i = 0; i < 16; i++) {
        const int off = i * 32 + ks * 4;
        const int v   = off >> 2;

        ulonglong2 xm1 = vA ? Pm1[v] : make_ulonglong2(0, 0);
        ulonglong2 x0  = P0[v];
        ulonglong2 x1  = P1[v];
        ulonglong2 x2  = P2[v];
        ulonglong2 x3  = vC ? P3[v] : make_ulonglong2(0, 0);

#pragma unroll
        for (int j = 0; j < 4; j++) {
            ulonglong2 wl = *(const ulonglong2*)(wl_base + j * E_DIM + off);
            ulonglong2 wh = *(const ulonglong2*)(wh_base + j * E_DIM + off);
            // pair0
            ffma2(a0[j], x0.x,  wl.x);  ffma2(a0[j], x0.y,  wl.y);
            ffma2(a0[j], xm1.x, wh.x);  ffma2(a0[j], xm1.y, wh.y);
            ffma2(a1[j], x1.x,  wl.x);  ffma2(a1[j], x1.y,  wl.y);
            ffma2(a1[j], x0.x,  wh.x);  ffma2(a1[j], x0.y,  wh.y);
            // pair1
            ffma2(b0[j], x2.x,  wl.x);  ffma2(b0[j], x2.y,  wl.y);
            ffma2(b0[j], x1.x,  wh.x);  ffma2(b0[j], x1.y,  wh.y);
            ffma2(b1[j], x3.x,  wl.x);  ffma2(b1[j], x3.y,  wl.y);
            ffma2(b1[j], x2.x,  wh.x);  ffma2(b1[j], x2.y,  wh.y);
        }
    }

    // horizontal packed add -> 16 floats, then reduce over the 8 ks lanes
    float s[16];
#pragma unroll
    for (int j = 0; j < 4; j++) {
        s[j]      = lo(a0[j]) + hi(a0[j]);
        s[4 + j]  = lo(a1[j]) + hi(a1[j]);
        s[8 + j]  = lo(b0[j]) + hi(b0[j]);
        s[12 + j] = lo(b1[j]) + hi(b1[j]);
    }
#pragma unroll
    for (int m = 1; m <= 4; m <<= 1) {
#pragma unroll
        for (int j = 0; j < 16; j++)
            s[j] += __shfl_xor_sync(0xffffffffu, s[j], m);
    }

    if (ks == 0) {
        // samples: a0[j] -> 16p0 + rb + j ; a1[j] -> 16p0 + 8 + rb + j
        //          b0[j] -> 16p0+16+rb+j ; b1[j] -> 16p0 + 24 + rb + j
        float* o = out + (size_t)bc * OUT_T + (size_t)p0 * 16 + rb;
        *(float4*)(o)      = make_float4(s[0],  s[1],  s[2],  s[3]);
        *(float4*)(o + 8)  = make_float4(s[4],  s[5],  s[6],  s[7]);
        *(float4*)(o + 16) = make_float4(s[8],  s[9],  s[10], s[11]);
        *(float4*)(o + 24) = make_float4(s[12], s[13], s[14], s[15]);
    }
}

extern "C" void kernel_launch(void* const* d_in, const int* in_sizes, int n_in,
                              void* d_out, int out_size)
{
    const float* x;
    const float* wt;
    if (in_sizes[0] > in_sizes[1]) { x = (const float*)d_in[0]; wt = (const float*)d_in[1]; }
    else                           { x = (const float*)d_in[1]; wt = (const float*)d_in[0]; }

    const int total_groups = N_BC * GROUPS;               // 16000
    const int grid = total_groups / GROUPS_PER_BLOCK;     // 1000 blocks
    decoder_oadd_kernel<<<grid, NTHREADS>>>(x, wt, (float*)d_out);
}

// round 7
// speedup vs baseline: 1.3772x; 1.0890x over previous
#include <cuda_runtime.h>
#include <cstdint>

// Custom_Decoder fused GEMM + overlap_add, cp.async ring-buffer version.
// out[bc,16p+r]   = x[2p].wt[r]   + x[2p-1].wt[8+r]
// out[bc,16p+8+r] = x[2p+1].wt[r] + x[2p]  .wt[8+r]
//
// Persistent blocks: 144 blocks x 7 units, unit = 32 pairs (64 frames) of one bc.
// Frames staged in K-halves through a 3-slot smem ring fed by cp.async.
// Slot = 65 frame-half rows (64 + 1 halo), invalid frames zero-filled.

#define E_DIM 512
#define HALF  256
#define FRAMES 3999
#define PAIRS 2000
#define OUT_T 32000
#define UNITS_PER_BC 63
#define GRID 144
#define UNITS_PER_BLOCK 7          // 144*7 = 1008 = 16*63
#define NSTAGES (2*UNITS_PER_BLOCK)
#define NTH 256
#define SLOT_BYTES (65*1024)       // 65 frame-half rows x 1KB
#define W_BYTES (16*E_DIM*4)       // 32768
#define SMEM_TOTAL (W_BYTES + 3*SLOT_BYTES)   // 232448 = sm_10x optin max
#define CHUNKS 4160                // SLOT_BYTES/16

typedef unsigned long long ull;

__device__ __forceinline__ void ffma2(ull &d, ull a, ull b) {
    asm("fma.rn.f32x2 %0, %1, %2, %0;" : "+l"(d) : "l"(a), "l"(b));
}
__device__ __forceinline__ float flo(ull v){ return __uint_as_float((unsigned)(v & 0xffffffffu)); }
__device__ __forceinline__ float fhi(ull v){ return __uint_as_float((unsigned)(v >> 32)); }

__device__ __forceinline__ void cp16(uint32_t sa, const void* g) {
    asm volatile("cp.async.cg.shared.global [%0], [%1], 16;" :: "r"(sa), "l"(g));
}
__device__ __forceinline__ void cp_commit() { asm volatile("cp.async.commit_group;"); }
__device__ __forceinline__ void cp_wait2()  { asm volatile("cp.async.wait_group 2;"); }

// issue loads for pipeline stage s (unit iu = s/2, k-half h = s&1); always commits
// (empty group past the end keeps wait_group(2) bookkeeping uniform).
__device__ __forceinline__ void issue_stage(char* ring, const float* __restrict__ x,
                                            int s, int tid, int bx)
{
    if (s < NSTAGES) {
        const int iu = s >> 1, h = s & 1;
        const int u  = bx + GRID * iu;           // < 1008
        const int bc = u / UNITS_PER_BC;
        const int U  = u - bc * UNITS_PER_BC;
        const int f0 = 64 * U - 1;               // first staged frame (may be -1)
        const float* xb = x + (size_t)bc * FRAMES * E_DIM + h * HALF;
        char* slot = ring + (s % 3) * SLOT_BYTES;
        uint32_t sbase = (uint32_t)__cvta_generic_to_shared(slot);
#pragma unroll
        for (int i = 0; i < 17; i++) {
            int c = tid + i * NTH;
            if (i < 16 || c < CHUNKS) {
                int j = c >> 6;                  // frame-half row 0..64
                int f = f0 + j;
                uint32_t sa = sbase + c * 16;
                if ((unsigned)f < FRAMES) {
                    cp16(sa, xb + (size_t)f * E_DIM + (c & 63) * 4);
                } else {
                    asm volatile("st.shared.v4.b32 [%0], {%1,%1,%1,%1};" :: "r"(sa), "r"(0));
                }
            }
        }
    }
    cp_commit();
}

__global__ __launch_bounds__(NTH)
void decoder_oadd_ring(const float* __restrict__ x,
                       const float* __restrict__ wt,
                       float* __restrict__ out)
{
    extern __shared__ __align__(16) char smem[];
    float* wsm = (float*)smem;
    char*  ring = smem + W_BYTES;

    const int tid = threadIdx.x;
    const int bx  = blockIdx.x;

    // stage weights (8 float4 per thread)
#pragma unroll
    for (int i = 0; i < (16 * E_DIM) / (4 * NTH); i++) {
        int idx = (i * NTH + tid) * 4;
        *(float4*)(wsm + idx) = *(const float4*)(wt + idx);
    }

    // prologue: prefetch stages 0,1,2
    issue_stage(ring, x, 0, tid, bx);
    issue_stage(ring, x, 1, tid, bx);
    issue_stage(ring, x, 2, tid, bx);

    const int ks = tid & 7;            // k slice
    const int rh = (tid >> 3) & 1;     // row half
    const int gl = tid >> 4;           // group (2 pairs) in block
    const int rb = rh * 4;

#pragma unroll 1
    for (int iu = 0; iu < UNITS_PER_BLOCK; iu++) {
        const int u  = bx + GRID * iu;
        const int bc = u / UNITS_PER_BC;
        const int U  = u - bc * UNITS_PER_BC;
        const int p0 = 32 * U + 2 * gl;          // this thread's first pair

        ull a0[4], a1[4], b0[4], b1[4];
#pragma unroll
        for (int j = 0; j < 4; j++) { a0[j]=0; a1[j]=0; b0[j]=0; b1[j]=0; }

#pragma unroll
        for (int h = 0; h < 2; h++) {
            const int s = 2 * iu + h;
            cp_wait2();
            __syncthreads();

            // rows j = 4gl .. 4gl+4 hold frames 2p0-1 .. 2p0+3 (zeros at edges)
            const char* xg = ring + (s % 3) * SLOT_BYTES + (4 * gl) * 1024 + ks * 16;
            const float* wA = wsm + rb * E_DIM + h * HALF + ks * 4;  // rows rb..rb+3
            const float* wB = wA + 8 * E_DIM;                        // rows rb+8..

#pragma unroll
            for (int i = 0; i < 8; i++) {
                const int xo = i * 128;
                ulonglong2 xm1 = *(const ulonglong2*)(xg +            xo);
                ulonglong2 x0  = *(const ulonglong2*)(xg + 1 * 1024 + xo);
                ulonglong2 x1  = *(const ulonglong2*)(xg + 2 * 1024 + xo);
                ulonglong2 x2  = *(const ulonglong2*)(xg + 3 * 1024 + xo);
                ulonglong2 x3  = *(const ulonglong2*)(xg + 4 * 1024 + xo);
#pragma unroll
                for (int j = 0; j < 4; j++) {
                    ulonglong2 wl = *(const ulonglong2*)(wA + j * E_DIM + i * 32);
                    ulonglong2 wh = *(const ulonglong2*)(wB + j * E_DIM + i * 32);
                    ffma2(a0[j], x0.x,  wl.x);  ffma2(a0[j], x0.y,  wl.y);
                    ffma2(a0[j], xm1.x, wh.x);  ffma2(a0[j], xm1.y, wh.y);
                    ffma2(a1[j], x1.x,  wl.x);  ffma2(a1[j], x1.y,  wl.y);
                    ffma2(a1[j], x0.x,  wh.x);  ffma2(a1[j], x0.y,  wh.y);
                    ffma2(b0[j], x2.x,  wl.x);  ffma2(b0[j], x2.y,  wl.y);
                    ffma2(b0[j], x1.x,  wh.x);  ffma2(b0[j], x1.y,  wh.y);
                    ffma2(b1[j], x3.x,  wl.x);  ffma2(b1[j], x3.y,  wl.y);
                    ffma2(b1[j], x2.x,  wh.x);  ffma2(b1[j], x2.y,  wh.y);
                }
            }
            __syncthreads();                 // slot fully consumed by all warps
            issue_stage(ring, x, s + 3, tid, bx);   // refill this slot (or empty commit)
        }

        // epilogue: packed horizontal add, reduce over 8 ks lanes, store
        float sv[16];
#pragma unroll
        for (int j = 0; j < 4; j++) {
            sv[j]      = flo(a0[j]) + fhi(a0[j]);
            sv[4 + j]  = flo(a1[j]) + fhi(a1[j]);
            sv[8 + j]  = flo(b0[j]) + fhi(b0[j]);
            sv[12 + j] = flo(b1[j]) + fhi(b1[j]);
        }
#pragma unroll
        for (int m = 1; m <= 4; m <<= 1)
#pragma unroll
            for (int j = 0; j < 16; j++)
                sv[j] += __shfl_xor_sync(0xffffffffu, sv[j], m);

        if (ks == 0 && p0 < PAIRS) {
            float* o = out + (size_t)bc * OUT_T + (size_t)p0 * 16 + rb;
            *(float4*)(o)      = make_float4(sv[0],  sv[1],  sv[2],  sv[3]);
            *(float4*)(o + 8)  = make_float4(sv[4],  sv[5],  sv[6],  sv[7]);
            *(float4*)(o + 16) = make_float4(sv[8],  sv[9],  sv[10], sv[11]);
            *(float4*)(o + 24) = make_float4(sv[12], sv[13], sv[14], sv[15]);
        }
    }
}

extern "C" void kernel_launch(void* const* d_in, const int* in_sizes, int n_in,
                              void* d_out, int out_size)
{
    const float *x, *wt;
    if (in_sizes[0] > in_sizes[1]) { x = (const float*)d_in[0]; wt = (const float*)d_in[1]; }
    else                           { x = (const float*)d_in[1]; wt = (const float*)d_in[0]; }

    // idempotent, executes eagerly even under graph capture
    cudaFuncSetAttribute(decoder_oadd_ring,
                         cudaFuncAttributeMaxDynamicSharedMemorySize, SMEM_TOTAL);

    decoder_oadd_ring<<<GRID, NTH, SMEM_TOTAL>>>(x, wt, (float*)d_out);
}